// round 9
// baseline (speedup 1.0000x reference)
#include <cuda_runtime.h>
#include <cuda_bf16.h>

#define NE 10
#define NBINS 11
#define THREADS 128
#define NWARP (THREADS / 32)
#define LOG2E 1.4426950408889634f
#define BOOST 120.0f
#define SPLIT 2

__device__ __forceinline__ float ex2f(float a) {
    float r; asm("ex2.approx.ftz.f32 %0, %1;" : "=f"(r) : "f"(a)); return r;
}
__device__ __forceinline__ float rcpf(float a) {
    float r; asm("rcp.approx.ftz.f32 %0, %1;" : "=f"(r) : "f"(a)); return r;
}

__global__ void zero_out_kernel(float* __restrict__ out, int n) {
    int i = blockIdx.x * blockDim.x + threadIdx.x;
    if (i < n) out[i] = 0.0f;
}

__global__ __launch_bounds__(THREADS, 10)
void hist_prof_kernel(const float* __restrict__ x,
                      const float* __restrict__ edges,
                      float* __restrict__ out,
                      int hw, int C) {
    const int blk = blockIdx.x;          // blk = bt*C + c
    const int seg = blockIdx.y;          // which hw segment
    const int c = blk % C;

    // this block's pixel segment [p0, p1) of the row, in float4 units
    const int n4 = hw >> 2;
    const int q0 = (n4 * seg) / SPLIT;
    const int q1 = (n4 * (seg + 1)) / SPLIT;
    const float4* __restrict__ xp4 = (const float4*)(x + (size_t)blk * hw);

    __shared__ float sE[NE];
    __shared__ float sred[NWARP][NBINS];

    if (threadIdx.x < NE) sE[threadIdx.x] = edges[(size_t)c * NE + threadIdx.x];
    __syncthreads();

    // ---- per-block constants (block-uniform -> UR-promotable) ----
    const float mu0 = sE[0];
    const float muA = 0.5f * (sE[1] + sE[2]);          // bin 2 center (anchor A)
    const float muB = 0.5f * (sE[6] + sE[7]);          // bin 7 center (anchor B)
    const float mu1 = 0.5f * (sE[0] + sE[1]);
    const float mu3 = 0.5f * (sE[2] + sE[3]);
    const float mu6 = 0.5f * (sE[5] + sE[6]);
    const float mu8 = 0.5f * (sE[7] + sE[8]);
    const float sig = (sE[0] - sE[1]) * (1.0f / 3.0f) + 1e-6f;   // same all bins
    const float kk2 = (0.5f * LOG2E) / (sig * sig);    // G_i = 2^(-kk2 (x-mu_i)^2)
    const float nkk2 = -kk2;
    const float d   = muB - mu6;                       // uniform interior spacing

    // anchor quadratics: e_i = nkk2*x^2 + p_i*x + q_i  (shared x^2)
    const float p0c = 2.0f * kk2 * mu0, q0c = BOOST - kk2 * mu0 * mu0;
    const float pA = 2.0f * kk2 * muA, qA = BOOST - kk2 * muA * muA;
    const float pB = 2.0f * kk2 * muB, qB = BOOST - kk2 * muB * muB;

    // up-step i->i+1 ratio: 2^(a_up*x - kk2*d*(mu_i+mu_{i+1}))
    const float a_up = 2.0f * kk2 * d;
    const float naup = -a_up;
    const float bupA = -kk2 * d * (muA + mu3);         // anchor A, step 2->3
    const float bdnA =  kk2 * d * (mu1 + muA);         // step 2->1 (down)
    const float bupB = -kk2 * d * (muB + mu8);         // anchor B, step 7->8
    const float bdnB =  kk2 * d * (mu6 + muB);         // step 7->6 (down)
    const float rho  = exp2f(-2.0f * kk2 * d * d);     // extra-step decay
    const float cUB  = exp2f(bupB - bupA);             // U_B = U_A * cUB
    const float cDB  = exp2f(bdnB - bdnA);             // D_B = D_A * cDB
    const float inv  = exp2f(-BOOST);

    // clamp so every ratio (incl. derived B ratios) stays <= 2^125
    const float xhi = (125.0f - bupA) / a_up;   // ~ +1.16
    const float xlo = (bdnB - 125.0f) / a_up;   // ~ -0.36

    // sigmoid tail on RAW x: 1/(1 + 2^(nCs*x + Cb)); inf -> rcp -> 0 correct
    const float nCs = -20.0f * LOG2E;
    const float Cb  =  20.0f * LOG2E * sE[NE - 1];

    float a0 = 0.f, a1 = 0.f, a2 = 0.f, a3 = 0.f, a4 = 0.f;
    float a5 = 0.f, a6 = 0.f, a7 = 0.f, a8 = 0.f, a9 = 0.f, aS = 0.f;

#define DO_PX(xv_) do {                                                         \
        float xv = (xv_);                                                       \
        float xc = fminf(fmaxf(xv, xlo), xhi);                                  \
        float x2 = xc * xc;                                                     \
        /* three boosted anchors via shared x^2 */                              \
        float e0 = fmaf(x2, nkk2, fmaf(xc, p0c, q0c));                          \
        float eA = fmaf(x2, nkk2, fmaf(xc, pA, qA));                            \
        float eB = fmaf(x2, nkk2, fmaf(xc, pB, qB));                            \
        float G0 = ex2f(e0);                                                    \
        float GA = ex2f(eA);                                                    \
        float GB = ex2f(eB);                                                    \
        /* ratios */                                                            \
        float UA = ex2f(fmaf(xc, a_up, bupA));                                  \
        float DA = ex2f(fmaf(xc, naup, bdnA));                                  \
        float UB = UA * cUB;                                                    \
        float DB = DA * cDB;                                                    \
        a0 += G0;                                                               \
        /* group A: anchor 2; 3,4 up; 1 down */                                 \
        a2 += GA;                                                               \
        float gA = GA * UA;        a3 += gA;                                    \
        float rA = UA * rho;       a4 = fmaf(gA, rA, a4);                       \
        a1 = fmaf(GA, DA, a1);                                                  \
        /* group B: anchor 7; 8,9 up; 6,5 down */                               \
        a7 += GB;                                                               \
        float gB = GB * UB;        a8 += gB;                                    \
        float rB = UB * rho;       a9 = fmaf(gB, rB, a9);                       \
        float hB = GB * DB;        a6 += hB;                                    \
        float sB = DB * rho;       a5 = fmaf(hB, sB, a5);                       \
        /* sigmoid tail on raw x */                                             \
        float ts = fmaf(xv, nCs, Cb);                                           \
        aS += rcpf(ex2f(ts) + 1.0f);                                            \
    } while (0)

    // main loop over this segment's float4s, coalesced
    for (int p = q0 + threadIdx.x; p < q1; p += THREADS) {
        float4 v = xp4[p];
        DO_PX(v.x);
        DO_PX(v.y);
        DO_PX(v.z);
        DO_PX(v.w);
    }
    // hw%4 tail pixels handled by segment SPLIT-1
    if (seg == SPLIT - 1) {
        const float* __restrict__ xp = (const float*)xp4;
        for (int p = (n4 << 2) + threadIdx.x; p < hw; p += THREADS) {
            DO_PX(xp[p]);
        }
    }
#undef DO_PX

    // ---- reduction: unboost, shuffle, cross-warp smem, atomic combine ----
    float accv[NBINS] = {a0, a1, a2, a3, a4, a5, a6, a7, a8, a9, aS};
#pragma unroll
    for (int i = 0; i < NBINS; i++) {
        float v = (i < NE) ? accv[i] * inv : accv[i];
        v += __shfl_down_sync(0xFFFFFFFFu, v, 16);
        v += __shfl_down_sync(0xFFFFFFFFu, v, 8);
        v += __shfl_down_sync(0xFFFFFFFFu, v, 4);
        v += __shfl_down_sync(0xFFFFFFFFu, v, 2);
        v += __shfl_down_sync(0xFFFFFFFFu, v, 1);
        if ((threadIdx.x & 31) == 0) sred[threadIdx.x >> 5][i] = v;
    }
    __syncthreads();
    if (threadIdx.x < NBINS) {
        float s = 0.0f;
#pragma unroll
        for (int w = 0; w < NWARP; w++) s += sred[w][threadIdx.x];
        atomicAdd(&out[(size_t)blk * NBINS + threadIdx.x], s);
    }
}

extern "C" void kernel_launch(void* const* d_in, const int* in_sizes, int n_in,
                              void* d_out, int out_size) {
    const float* x     = (const float*)d_in[0];
    const float* edges = (const float*)d_in[1];
    float* out = (float*)d_out;

    const int n_bc = out_size / NBINS;          // bt * c
    const int hw   = in_sizes[0] / n_bc;        // h * w
    const int C    = in_sizes[1] / NE;          // channels

    zero_out_kernel<<<(out_size + 255) / 256, 256>>>(out, out_size);
    dim3 grid(n_bc, SPLIT);
    hist_prof_kernel<<<grid, THREADS>>>(x, edges, out, hw, C);
}

// round 11
// speedup vs baseline: 1.1008x; 1.1008x over previous
#include <cuda_runtime.h>
#include <cuda_bf16.h>

#define NE 10
#define NBINS 11
#define THREADS 128
#define NWARP (THREADS / 32)
#define LOG2E 1.4426950408889634f
#define BOOST 120.0f

__device__ __forceinline__ float ex2f(float a) {
    float r; asm("ex2.approx.ftz.f32 %0, %1;" : "=f"(r) : "f"(a)); return r;
}
__device__ __forceinline__ float rcpf(float a) {
    float r; asm("rcp.approx.ftz.f32 %0, %1;" : "=f"(r) : "f"(a)); return r;
}

__global__ __launch_bounds__(THREADS, 12)
void hist_prof_kernel(const float* __restrict__ x,
                      const float* __restrict__ edges,
                      float* __restrict__ out,
                      int hw, int C) {
    const int blk = blockIdx.x;          // blk = bt*C + c
    const int c = blk % C;
    const float* __restrict__ xp = x + (size_t)blk * hw;

    __shared__ float sE[NE];
    __shared__ float sred[NWARP][NBINS];

    if (threadIdx.x < NE) sE[threadIdx.x] = edges[(size_t)c * NE + threadIdx.x];
    __syncthreads();

    // ---- per-block constants (block-uniform -> UR-promotable) ----
    const float mu0 = sE[0];
    const float muA = 0.5f * (sE[1] + sE[2]);          // bin 2 center (anchor A)
    const float muB = 0.5f * (sE[6] + sE[7]);          // bin 7 center (anchor B)
    const float mu1 = 0.5f * (sE[0] + sE[1]);
    const float mu3 = 0.5f * (sE[2] + sE[3]);
    const float mu6 = 0.5f * (sE[5] + sE[6]);
    const float mu8 = 0.5f * (sE[7] + sE[8]);
    const float sig = (sE[0] - sE[1]) * (1.0f / 3.0f) + 1e-6f;   // same all bins
    const float kk2 = (0.5f * LOG2E) / (sig * sig);    // G_i = 2^(-kk2 (x-mu_i)^2)
    const float nkk2 = -kk2;
    const float d   = muB - mu6;                       // uniform interior spacing

    // anchor quadratics: e_i = nkk2*x^2 + p_i*x + q_i  (shared x^2)
    const float p0c = 2.0f * kk2 * mu0, q0c = BOOST - kk2 * mu0 * mu0;
    const float pA = 2.0f * kk2 * muA, qA = BOOST - kk2 * muA * muA;
    const float pB = 2.0f * kk2 * muB, qB = BOOST - kk2 * muB * muB;

    // up-step i->i+1 ratio: 2^(a_up*x - kk2*d*(mu_i+mu_{i+1}))
    const float a_up = 2.0f * kk2 * d;
    const float naup = -a_up;
    const float bupA = -kk2 * d * (muA + mu3);         // anchor A, step 2->3
    const float bdnA =  kk2 * d * (mu1 + muA);         // step 2->1 (down)
    const float bupB = -kk2 * d * (muB + mu8);         // anchor B, step 7->8
    const float bdnB =  kk2 * d * (mu6 + muB);         // step 7->6 (down)
    const float rho  = exp2f(-2.0f * kk2 * d * d);     // extra-step decay
    const float cUB  = exp2f(bupB - bupA);             // U_B = U_A * cUB
    const float cDB  = exp2f(bdnB - bdnA);             // D_B = D_A * cDB
    const float inv  = exp2f(-BOOST);

    // clamp so every ratio (incl. derived B ratios) stays <= 2^125
    const float xhi = (125.0f - bupA) / a_up;   // ~ +1.16
    const float xlo = (bdnB - 125.0f) / a_up;   // ~ -0.36

    // sigmoid tail on RAW x: 1/(1 + 2^(nCs*x + Cb)); inf -> rcp -> 0 correct
    const float nCs = -20.0f * LOG2E;
    const float Cb  =  20.0f * LOG2E * sE[NE - 1];

    float a0 = 0.f, a1 = 0.f, a2 = 0.f, a3 = 0.f, a4 = 0.f;
    float a5 = 0.f, a6 = 0.f, a7 = 0.f, a8 = 0.f, a9 = 0.f, aS = 0.f;

#define DO_PX(xv_) do {                                                         \
        float xv = (xv_);                                                       \
        float xc = fminf(fmaxf(xv, xlo), xhi);                                  \
        float x2 = xc * xc;                                                     \
        /* three boosted anchors via shared x^2 */                              \
        float e0 = fmaf(x2, nkk2, fmaf(xc, p0c, q0c));                          \
        float eA = fmaf(x2, nkk2, fmaf(xc, pA, qA));                            \
        float eB = fmaf(x2, nkk2, fmaf(xc, pB, qB));                            \
        float G0 = ex2f(e0);                                                    \
        float GA = ex2f(eA);                                                    \
        float GB = ex2f(eB);                                                    \
        /* ratios */                                                            \
        float UA = ex2f(fmaf(xc, a_up, bupA));                                  \
        float DA = ex2f(fmaf(xc, naup, bdnA));                                  \
        float UB = UA * cUB;                                                    \
        float DB = DA * cDB;                                                    \
        a0 += G0;                                                               \
        /* group A: anchor 2; 3,4 up; 1 down */                                 \
        a2 += GA;                                                               \
        float gA = GA * UA;        a3 += gA;                                    \
        float rA = UA * rho;       a4 = fmaf(gA, rA, a4);                       \
        a1 = fmaf(GA, DA, a1);                                                  \
        /* group B: anchor 7; 8,9 up; 6,5 down */                               \
        a7 += GB;                                                               \
        float gB = GB * UB;        a8 += gB;                                    \
        float rB = UB * rho;       a9 = fmaf(gB, rB, a9);                       \
        float hB = GB * DB;        a6 += hB;                                    \
        float sB = DB * rho;       a5 = fmaf(hB, sB, a5);                       \
        /* sigmoid tail on raw x */                                             \
        float ts = fmaf(xv, nCs, Cb);                                           \
        aS += rcpf(ex2f(ts) + 1.0f);                                            \
    } while (0)

    // main loop: float4, coalesced; 4 independent pixel chains per iteration
    const int n4 = hw >> 2;
    const float4* __restrict__ xp4 = (const float4*)xp;
    for (int p = threadIdx.x; p < n4; p += THREADS) {
        float4 v = xp4[p];
        DO_PX(v.x);
        DO_PX(v.y);
        DO_PX(v.z);
        DO_PX(v.w);
    }
    // tail (hw % 4; unused for hw=3136)
    for (int p = (n4 << 2) + threadIdx.x; p < hw; p += THREADS) {
        DO_PX(xp[p]);
    }
#undef DO_PX

    // ---- reduction: unboost, shuffle, cross-warp smem ----
    float accv[NBINS] = {a0, a1, a2, a3, a4, a5, a6, a7, a8, a9, aS};
#pragma unroll
    for (int i = 0; i < NBINS; i++) {
        float v = (i < NE) ? accv[i] * inv : accv[i];
        v += __shfl_down_sync(0xFFFFFFFFu, v, 16);
        v += __shfl_down_sync(0xFFFFFFFFu, v, 8);
        v += __shfl_down_sync(0xFFFFFFFFu, v, 4);
        v += __shfl_down_sync(0xFFFFFFFFu, v, 2);
        v += __shfl_down_sync(0xFFFFFFFFu, v, 1);
        if ((threadIdx.x & 31) == 0) sred[threadIdx.x >> 5][i] = v;
    }
    __syncthreads();
    if (threadIdx.x < NBINS) {
        float s = 0.0f;
#pragma unroll
        for (int w = 0; w < NWARP; w++) s += sred[w][threadIdx.x];
        out[(size_t)blk * NBINS + threadIdx.x] = s;
    }
}

extern "C" void kernel_launch(void* const* d_in, const int* in_sizes, int n_in,
                              void* d_out, int out_size) {
    const float* x     = (const float*)d_in[0];
    const float* edges = (const float*)d_in[1];
    float* out = (float*)d_out;

    const int n_bc = out_size / NBINS;          // bt * c
    const int hw   = in_sizes[0] / n_bc;        // h * w
    const int C    = in_sizes[1] / NE;          // channels

    hist_prof_kernel<<<n_bc, THREADS>>>(x, edges, out, hw, C);
}

// round 12
// speedup vs baseline: 1.2014x; 1.0914x over previous
#include <cuda_runtime.h>
#include <cuda_bf16.h>

#define NE 10
#define NBINS 11
#define THREADS 128
#define NWARP (THREADS / 32)
#define LOG2E 1.4426950408889634f
#define BOOST 120.0f

__device__ __forceinline__ float ex2f(float a) {
    float r; asm("ex2.approx.ftz.f32 %0, %1;" : "=f"(r) : "f"(a)); return r;
}
__device__ __forceinline__ float tanhf_hw(float a) {
    float r; asm("tanh.approx.f32 %0, %1;" : "=f"(r) : "f"(a)); return r;
}

__global__ __launch_bounds__(THREADS, 10)
void hist_prof_kernel(const float* __restrict__ x,
                      const float* __restrict__ edges,
                      float* __restrict__ out,
                      int hw, int C) {
    const int blk = blockIdx.x;          // blk = bt*C + c
    const int c = blk % C;
    const float* __restrict__ xp = x + (size_t)blk * hw;

    __shared__ float sE[NE];
    __shared__ float sred[NWARP][NBINS];

    if (threadIdx.x < NE) sE[threadIdx.x] = edges[(size_t)c * NE + threadIdx.x];
    __syncthreads();

    // ---- per-block constants (block-uniform -> UR-promotable) ----
    const float mu0 = sE[0];
    const float muA = 0.5f * (sE[1] + sE[2]);          // bin 2 center (anchor A)
    const float muB = 0.5f * (sE[6] + sE[7]);          // bin 7 center (anchor B)
    const float mu1 = 0.5f * (sE[0] + sE[1]);
    const float mu3 = 0.5f * (sE[2] + sE[3]);
    const float mu6 = 0.5f * (sE[5] + sE[6]);
    const float mu8 = 0.5f * (sE[7] + sE[8]);
    const float sig = (sE[0] - sE[1]) * (1.0f / 3.0f) + 1e-6f;   // same all bins
    const float kk2 = (0.5f * LOG2E) / (sig * sig);    // G_i = 2^(-kk2 (x-mu_i)^2)
    const float nkk2 = -kk2;
    const float d   = muB - mu6;                       // uniform interior spacing

    // anchor quadratics: e_i = nkk2*x^2 + p_i*x + q_i  (shared x^2)
    const float p0c = 2.0f * kk2 * mu0, q0c = BOOST - kk2 * mu0 * mu0;
    const float pA = 2.0f * kk2 * muA, qA = BOOST - kk2 * muA * muA;
    const float pB = 2.0f * kk2 * muB, qB = BOOST - kk2 * muB * muB;

    // up-step i->i+1 ratio: 2^(a_up*x - kk2*d*(mu_i+mu_{i+1}))
    const float a_up = 2.0f * kk2 * d;
    const float naup = -a_up;
    const float bupA = -kk2 * d * (muA + mu3);         // anchor A, step 2->3
    const float bdnA =  kk2 * d * (mu1 + muA);         // step 2->1 (down)
    const float bupB = -kk2 * d * (muB + mu8);         // anchor B, step 7->8
    const float bdnB =  kk2 * d * (mu6 + muB);         // step 7->6 (down)
    const float rho  = exp2f(-2.0f * kk2 * d * d);     // extra-step decay
    const float cUB  = exp2f(bupB - bupA);             // U_B = U_A * cUB
    const float cDB  = exp2f(bdnB - bdnA);             // D_B = D_A * cDB
    const float inv  = exp2f(-BOOST);

    // clamp so every ratio (incl. derived B ratios) stays <= 2^125
    const float xhi = (125.0f - bupA) / a_up;   // ~ +1.16
    const float xlo = (bdnB - 125.0f) / a_up;   // ~ -0.36

    // sigmoid tail on RAW x via hw tanh:
    // sigmoid(20(x-e9)) = 0.5 + 0.5*tanh(10*(x-e9))
    const float tS = 10.0f;
    const float tB = -10.0f * sE[NE - 1];

    float a0 = 0.f, a1 = 0.f, a2 = 0.f, a3 = 0.f, a4 = 0.f;
    float a5 = 0.f, a6 = 0.f, a7 = 0.f, a8 = 0.f, a9 = 0.f, aS = 0.f;
    int pxcnt = 0;

#define DO_PX(xv_) do {                                                         \
        float xv = (xv_);                                                       \
        float xc = fminf(fmaxf(xv, xlo), xhi);                                  \
        float x2 = xc * xc;                                                     \
        /* three boosted anchors via shared x^2 */                              \
        float e0 = fmaf(x2, nkk2, fmaf(xc, p0c, q0c));                          \
        float eA = fmaf(x2, nkk2, fmaf(xc, pA, qA));                            \
        float eB = fmaf(x2, nkk2, fmaf(xc, pB, qB));                            \
        float G0 = ex2f(e0);                                                    \
        float GA = ex2f(eA);                                                    \
        float GB = ex2f(eB);                                                    \
        /* ratios */                                                            \
        float UA = ex2f(fmaf(xc, a_up, bupA));                                  \
        float DA = ex2f(fmaf(xc, naup, bdnA));                                  \
        float UB = UA * cUB;                                                    \
        float DB = DA * cDB;                                                    \
        a0 += G0;                                                               \
        /* group A: anchor 2; 3,4 up; 1 down */                                 \
        a2 += GA;                                                               \
        float gA = GA * UA;        a3 += gA;                                    \
        float rA = UA * rho;       a4 = fmaf(gA, rA, a4);                       \
        a1 = fmaf(GA, DA, a1);                                                  \
        /* group B: anchor 7; 8,9 up; 6,5 down */                               \
        a7 += GB;                                                               \
        float gB = GB * UB;        a8 += gB;                                    \
        float rB = UB * rho;       a9 = fmaf(gB, rB, a9);                       \
        float hB = GB * DB;        a6 += hB;                                    \
        float sB = DB * rho;       a5 = fmaf(hB, sB, a5);                       \
        /* sigmoid tail on raw x: accumulate tanh only */                       \
        aS += tanhf_hw(fmaf(xv, tS, tB));                                       \
    } while (0)

    // main loop: float4, coalesced; 4 independent pixel chains per iteration
    const int n4 = hw >> 2;
    const float4* __restrict__ xp4 = (const float4*)xp;
    for (int p = threadIdx.x; p < n4; p += THREADS) {
        float4 v = xp4[p];
        DO_PX(v.x);
        DO_PX(v.y);
        DO_PX(v.z);
        DO_PX(v.w);
    }
    // per-thread pixel count for the main loop (no per-iteration cost)
    if ((int)threadIdx.x < n4)
        pxcnt = 4 * ((n4 - (int)threadIdx.x + THREADS - 1) / THREADS);
    // tail (hw % 4; unused for hw=3136)
    for (int p = (n4 << 2) + threadIdx.x; p < hw; p += THREADS) {
        DO_PX(xp[p]);
        pxcnt++;
    }
#undef DO_PX

    // ---- reduction: unboost, shuffle, cross-warp smem ----
    // last bin: sum sigmoid = 0.5*(pxcnt + sum tanh)
    float accv[NBINS] = {a0, a1, a2, a3, a4, a5, a6, a7, a8, a9,
                         0.5f * ((float)pxcnt + aS)};
#pragma unroll
    for (int i = 0; i < NBINS; i++) {
        float v = (i < NE) ? accv[i] * inv : accv[i];
        v += __shfl_down_sync(0xFFFFFFFFu, v, 16);
        v += __shfl_down_sync(0xFFFFFFFFu, v, 8);
        v += __shfl_down_sync(0xFFFFFFFFu, v, 4);
        v += __shfl_down_sync(0xFFFFFFFFu, v, 2);
        v += __shfl_down_sync(0xFFFFFFFFu, v, 1);
        if ((threadIdx.x & 31) == 0) sred[threadIdx.x >> 5][i] = v;
    }
    __syncthreads();
    if (threadIdx.x < NBINS) {
        float s = 0.0f;
#pragma unroll
        for (int w = 0; w < NWARP; w++) s += sred[w][threadIdx.x];
        out[(size_t)blk * NBINS + threadIdx.x] = s;
    }
}

extern "C" void kernel_launch(void* const* d_in, const int* in_sizes, int n_in,
                              void* d_out, int out_size) {
    const float* x     = (const float*)d_in[0];
    const float* edges = (const float*)d_in[1];
    float* out = (float*)d_out;

    const int n_bc = out_size / NBINS;          // bt * c
    const int hw   = in_sizes[0] / n_bc;        // h * w
    const int C    = in_sizes[1] / NE;          // channels

    hist_prof_kernel<<<n_bc, THREADS>>>(x, edges, out, hw, C);
}

// round 13
// speedup vs baseline: 1.2326x; 1.0260x over previous
#include <cuda_runtime.h>
#include <cuda_bf16.h>

#define NE 10
#define NBINS 11
#define THREADS 128
#define NWARP (THREADS / 32)
#define LOG2E 1.4426950408889634f
#define BOOST 120.0f

__device__ __forceinline__ float ex2f(float a) {
    float r; asm("ex2.approx.ftz.f32 %0, %1;" : "=f"(r) : "f"(a)); return r;
}
__device__ __forceinline__ float tanhf_hw(float a) {
    float r; asm("tanh.approx.f32 %0, %1;" : "=f"(r) : "f"(a)); return r;
}

__global__ __launch_bounds__(THREADS, 9)
void hist_prof_kernel(const float* __restrict__ x,
                      const float* __restrict__ edges,
                      float* __restrict__ out,
                      int hw, int C) {
    const int blk = blockIdx.x;          // blk = bt*C + c
    const int c = blk % C;
    const float* __restrict__ xp = x + (size_t)blk * hw;

    __shared__ float sE[NE];
    __shared__ float sred[NWARP][NBINS];

    if (threadIdx.x < NE) sE[threadIdx.x] = edges[(size_t)c * NE + threadIdx.x];
    __syncthreads();

    // ---- per-block constants (block-uniform -> UR-promotable) ----
    const float mu0 = sE[0];
    const float muA = 0.5f * (sE[1] + sE[2]);          // bin 2 center (anchor A)
    const float muB = 0.5f * (sE[6] + sE[7]);          // bin 7 center (anchor B)
    const float mu1 = 0.5f * (sE[0] + sE[1]);
    const float mu3 = 0.5f * (sE[2] + sE[3]);
    const float mu6 = 0.5f * (sE[5] + sE[6]);
    const float mu8 = 0.5f * (sE[7] + sE[8]);
    const float sig = (sE[0] - sE[1]) * (1.0f / 3.0f) + 1e-6f;   // same all bins
    const float kk2 = (0.5f * LOG2E) / (sig * sig);    // G_i = 2^(-kk2 (x-mu_i)^2)
    const float nkk2 = -kk2;
    const float d   = muB - mu6;                       // uniform interior spacing

    // anchor quadratics: e_i = nkk2*x^2 + p_i*x + q_i  (shared x^2)
    const float p0c = 2.0f * kk2 * mu0, q0c = BOOST - kk2 * mu0 * mu0;
    const float pA = 2.0f * kk2 * muA, qA = BOOST - kk2 * muA * muA;
    const float pB = 2.0f * kk2 * muB, qB = BOOST - kk2 * muB * muB;

    // up-step i->i+1 ratio: 2^(a_up*x - kk2*d*(mu_i+mu_{i+1}))
    const float a_up = 2.0f * kk2 * d;
    const float naup = -a_up;
    const float bupA = -kk2 * d * (muA + mu3);         // anchor A, step 2->3
    const float bdnA =  kk2 * d * (mu1 + muA);         // step 2->1 (down)
    const float bupB = -kk2 * d * (muB + mu8);         // anchor B, step 7->8
    const float bdnB =  kk2 * d * (mu6 + muB);         // step 7->6 (down)
    const float rho  = exp2f(-2.0f * kk2 * d * d);     // extra-step decay
    const float cUB  = exp2f(bupB - bupA);             // U_B = U_A * cUB
    const float cDB  = exp2f(bdnB - bdnA);             // D_B = D_A * cDB
    const float inv  = exp2f(-BOOST);

    // clamp so every ratio (incl. derived B ratios) stays <= 2^125
    const float xhi = (125.0f - bupA) / a_up;   // ~ +1.16
    const float xlo = (bdnB - 125.0f) / a_up;   // ~ -0.36

    // sigmoid tail on RAW x via hw tanh:
    // sigmoid(20(x-e9)) = 0.5 + 0.5*tanh(10*(x-e9))
    const float tS = 10.0f;
    const float tB = -10.0f * sE[NE - 1];

    float a0 = 0.f, a1 = 0.f, a2 = 0.f, a3 = 0.f, a4 = 0.f;
    float a5 = 0.f, a6 = 0.f, a7 = 0.f, a8 = 0.f, a9 = 0.f, aS = 0.f;
    int pxcnt = 0;

#define DO_PX(xv_) do {                                                         \
        float xv = (xv_);                                                       \
        float xc = fminf(fmaxf(xv, xlo), xhi);                                  \
        float x2 = xc * xc;                                                     \
        /* three boosted anchors via shared x^2 */                              \
        float e0 = fmaf(x2, nkk2, fmaf(xc, p0c, q0c));                          \
        float eA = fmaf(x2, nkk2, fmaf(xc, pA, qA));                            \
        float eB = fmaf(x2, nkk2, fmaf(xc, pB, qB));                            \
        float G0 = ex2f(e0);                                                    \
        float GA = ex2f(eA);                                                    \
        float GB = ex2f(eB);                                                    \
        /* ratios */                                                            \
        float UA = ex2f(fmaf(xc, a_up, bupA));                                  \
        float DA = ex2f(fmaf(xc, naup, bdnA));                                  \
        float UB = UA * cUB;                                                    \
        float DB = DA * cDB;                                                    \
        a0 += G0;                                                               \
        /* group A: anchor 2; 3,4 up; 1 down */                                 \
        a2 += GA;                                                               \
        float gA = GA * UA;        a3 += gA;                                    \
        float rA = UA * rho;       a4 = fmaf(gA, rA, a4);                       \
        a1 = fmaf(GA, DA, a1);                                                  \
        /* group B: anchor 7; 8,9 up; 6,5 down */                               \
        a7 += GB;                                                               \
        float gB = GB * UB;        a8 += gB;                                    \
        float rB = UB * rho;       a9 = fmaf(gB, rB, a9);                       \
        float hB = GB * DB;        a6 += hB;                                    \
        float sB = DB * rho;       a5 = fmaf(hB, sB, a5);                       \
        /* sigmoid tail on raw x: accumulate tanh only */                       \
        aS += tanhf_hw(fmaf(xv, tS, tB));                                       \
    } while (0)

    // main loop: float4, coalesced, software-pipelined (prefetch next tile)
    const int n4 = hw >> 2;
    const float4* __restrict__ xp4 = (const float4*)xp;
    {
        int p = threadIdx.x;
        if (p < n4) {
            float4 v = xp4[p];
            for (;;) {
                const int pn = p + THREADS;
                const bool more = pn < n4;
                float4 vn = v;
                if (more) vn = xp4[pn];      // prefetch before the body
                DO_PX(v.x);
                DO_PX(v.y);
                DO_PX(v.z);
                DO_PX(v.w);
                if (!more) break;
                v = vn;
                p = pn;
            }
            pxcnt = 4 * ((n4 - (int)threadIdx.x + THREADS - 1) / THREADS);
        }
    }
    // tail (hw % 4; unused for hw=3136)
    for (int p = (n4 << 2) + threadIdx.x; p < hw; p += THREADS) {
        DO_PX(xp[p]);
        pxcnt++;
    }
#undef DO_PX

    // ---- reduction: unboost, shuffle, cross-warp smem ----
    // last bin: sum sigmoid = 0.5*(pxcnt + sum tanh)
    float accv[NBINS] = {a0, a1, a2, a3, a4, a5, a6, a7, a8, a9,
                         0.5f * ((float)pxcnt + aS)};
#pragma unroll
    for (int i = 0; i < NBINS; i++) {
        float v = (i < NE) ? accv[i] * inv : accv[i];
        v += __shfl_down_sync(0xFFFFFFFFu, v, 16);
        v += __shfl_down_sync(0xFFFFFFFFu, v, 8);
        v += __shfl_down_sync(0xFFFFFFFFu, v, 4);
        v += __shfl_down_sync(0xFFFFFFFFu, v, 2);
        v += __shfl_down_sync(0xFFFFFFFFu, v, 1);
        if ((threadIdx.x & 31) == 0) sred[threadIdx.x >> 5][i] = v;
    }
    __syncthreads();
    if (threadIdx.x < NBINS) {
        float s = 0.0f;
#pragma unroll
        for (int w = 0; w < NWARP; w++) s += sred[w][threadIdx.x];
        out[(size_t)blk * NBINS + threadIdx.x] = s;
    }
}

extern "C" void kernel_launch(void* const* d_in, const int* in_sizes, int n_in,
                              void* d_out, int out_size) {
    const float* x     = (const float*)d_in[0];
    const float* edges = (const float*)d_in[1];
    float* out = (float*)d_out;

    const int n_bc = out_size / NBINS;          // bt * c
    const int hw   = in_sizes[0] / n_bc;        // h * w
    const int C    = in_sizes[1] / NE;          // channels

    hist_prof_kernel<<<n_bc, THREADS>>>(x, edges, out, hw, C);
}